// round 16
// baseline (speedup 1.0000x reference)
#include <cuda_runtime.h>
#include <cuda_fp16.h>
#include <math.h>
#include <stdint.h>

#define BTOK 4096
#define DDIM 2048
#define HDIM 4096
#define NEXP 8

// ---------------------------------------------------------------------------
// Device-global scratch (no allocation allowed)
// ---------------------------------------------------------------------------
__device__ int    d_cnt[NEXP];
__device__ int    d_tok[NEXP * BTOK];
__device__ float  d_wt [NEXP * BTOK];
__device__ __half d_Xh [(size_t)BTOK * DDIM];          // fp16 activations (16MB)
__device__ __half d_Wh [(size_t)NEXP * HDIM * DDIM];   // fp16 weights (128MB)

// ---------------------------------------------------------------------------
// helpers
// ---------------------------------------------------------------------------
__device__ __forceinline__ uint32_t smem_u32(const void* p) {
    uint32_t a;
    asm("{ .reg .u64 t; cvta.to.shared.u64 t, %1; cvt.u32.u64 %0, t; }" : "=r"(a) : "l"(p));
    return a;
}
#define CPASYNC16(dst, src) \
    asm volatile("cp.async.cg.shared.global [%0], [%1], 16;" :: "r"(dst), "l"(src))
#define CPCOMMIT() asm volatile("cp.async.commit_group;" ::: "memory")
#define CPWAIT(n)  asm volatile("cp.async.wait_group %0;" :: "n"(n) : "memory")

__device__ __forceinline__ void ldsm_x4(uint32_t& r0, uint32_t& r1,
                                        uint32_t& r2, uint32_t& r3, uint32_t addr) {
    asm volatile("ldmatrix.sync.aligned.m8n8.x4.shared.b16 {%0,%1,%2,%3}, [%4];"
                 : "=r"(r0), "=r"(r1), "=r"(r2), "=r"(r3) : "r"(addr));
}

__device__ __forceinline__ void mma_f16(float* c, const uint32_t* a, const uint32_t* b) {
    asm volatile(
        "mma.sync.aligned.m16n8k16.row.col.f32.f16.f16.f32 "
        "{%0,%1,%2,%3}, {%4,%5,%6,%7}, {%8,%9}, {%0,%1,%2,%3};"
        : "+f"(c[0]), "+f"(c[1]), "+f"(c[2]), "+f"(c[3])
        : "r"(a[0]), "r"(a[1]), "r"(a[2]), "r"(a[3]), "r"(b[0]), "r"(b[1]));
}

__device__ __forceinline__ uint2 cvt_f4(float4 v) {
    __half2 h0 = __floats2half2_rn(v.x, v.y);
    __half2 h1 = __floats2half2_rn(v.z, v.w);
    return make_uint2(*(uint32_t*)&h0, *(uint32_t*)&h1);
}

// ---------------------------------------------------------------------------
// Kernel 1: fused prep — role split by blockIdx.x (frozen: at DRAM roofline)
//   [0, GATE_B)      : gate + emit fp16 x row (xconv folded in)
//   [+, ZERO_B)      : zero output main region (4-wide unrolled)
//   [+, WC_B)        : W -> fp16 (4-wide unrolled, MLP=4)
// ---------------------------------------------------------------------------
#define GATE_B 4096
#define ZERO_B 1024
#define WC_B   4096
#define PREP_B (GATE_B + ZERO_B + WC_B)

__global__ __launch_bounds__(256) void prep_kernel(
    const float* __restrict__ x, const int* __restrict__ labels,
    const float* __restrict__ emb, const float* __restrict__ gw,
    const float* __restrict__ gb, const float* __restrict__ eW,
    float* __restrict__ out, float* __restrict__ out_tail)
{
    const int bid = blockIdx.x;
    const int tid = threadIdx.x;

    if (bid >= GATE_B) {
        int r = bid - GATE_B;
        if (r < ZERO_B) {
            float4* o4 = (float4*)out;
            const size_t stride = (size_t)ZERO_B * 256;
            size_t base = (size_t)r * 256 + tid;
            const float4 z = make_float4(0.f, 0.f, 0.f, 0.f);
#pragma unroll
            for (int it = 0; it < 4; it++) {
                o4[base]              = z;
                o4[base + stride]     = z;
                o4[base + 2 * stride] = z;
                o4[base + 3 * stride] = z;
                base += 4 * stride;
            }
            return;
        }
        r -= ZERO_B;
        {
            const float4* W4 = (const float4*)eW;
            uint2* D4 = (uint2*)d_Wh;
            const size_t stride = (size_t)WC_B * 256;
            size_t base = (size_t)r * 256 + tid;
#pragma unroll
            for (int it = 0; it < 4; it++) {
                float4 v0 = W4[base];
                float4 v1 = W4[base + stride];
                float4 v2 = W4[base + 2 * stride];
                float4 v3 = W4[base + 3 * stride];
                D4[base]              = cvt_f4(v0);
                D4[base + stride]     = cvt_f4(v1);
                D4[base + 2 * stride] = cvt_f4(v2);
                D4[base + 3 * stride] = cvt_f4(v3);
                base += 4 * stride;
            }
            return;
        }
    }

    // ---- gate role (+ fp16 x emission) ----
    const int b = bid;
    const float4* xr = (const float4*)(x   + (size_t)b * DDIM);
    const float4* er = (const float4*)(emb + (size_t)labels[b] * DDIM);
    uint2* xh = (uint2*)(d_Xh + (size_t)b * DDIM);

    float acc[NEXP];
#pragma unroll
    for (int e = 0; e < NEXP; e++) acc[e] = 0.f;

    for (int j = tid; j < DDIM / 4; j += 256) {
        float4 xv = xr[j];
        float4 ev = er[j];
        xh[j] = cvt_f4(xv);
#pragma unroll
        for (int e = 0; e < NEXP; e++) {
            const float4* g  = (const float4*)(gw + (size_t)e * 2 * DDIM);
            float4 g1 = g[j];
            float4 g2 = g[DDIM / 4 + j];
            acc[e] += xv.x * g1.x + xv.y * g1.y + xv.z * g1.z + xv.w * g1.w
                    + ev.x * g2.x + ev.y * g2.y + ev.z * g2.z + ev.w * g2.w;
        }
    }
#pragma unroll
    for (int e = 0; e < NEXP; e++)
#pragma unroll
        for (int o = 16; o > 0; o >>= 1)
            acc[e] += __shfl_xor_sync(0xffffffffu, acc[e], o);

    __shared__ float red[8][NEXP];
    const int w = tid >> 5, l = tid & 31;
    if (l == 0) {
#pragma unroll
        for (int e = 0; e < NEXP; e++) red[w][e] = acc[e];
    }
    __syncthreads();

    if (tid == 0) {
        float lg[NEXP];
#pragma unroll
        for (int e = 0; e < NEXP; e++) {
            float s = gb[e];
#pragma unroll
            for (int ww = 0; ww < 8; ww++) s += red[ww][e];
            lg[e] = s;
        }
        int i0 = 0;
#pragma unroll
        for (int e = 1; e < NEXP; e++) if (lg[e] > lg[i0]) i0 = e;
        int i1 = -1;
#pragma unroll
        for (int e = 0; e < NEXP; e++) {
            if (e == i0) continue;
            if (i1 < 0 || lg[e] > lg[i1]) i1 = e;
        }
        float p0 = 1.f / (1.f + expf(lg[i1] - lg[i0]));
        float p1 = 1.f - p0;

        int s0 = atomicAdd(&d_cnt[i0], 1);
        d_tok[i0 * BTOK + s0] = b;
        d_wt [i0 * BTOK + s0] = p0;
        int s1 = atomicAdd(&d_cnt[i1], 1);
        d_tok[i1 * BTOK + s1] = b;
        d_wt [i1 * BTOK + s1] = p1;

        if (out_tail) {
            out_tail[2 * b + 0] = (float)i0;
            out_tail[2 * b + 1] = (float)i1;
        }
    }
}

// ---------------------------------------------------------------------------
// Kernel 2: grouped fp16 mma.sync GEMM + weighted combine.
// Tile 128x128x64, 3-stage cp.async, 2 CTAs/SM. Per-warp ks-stagger to
// de-correlate LDS bursts from MMA bursts across warps.
// grid: (HDIM/128, BTOK/128, NEXP)
// ---------------------------------------------------------------------------
#define BM 128
#define BN 128
#define BK 64                      // halves; row = 128B
#define NCH (DDIM / BK)            // 32
#define NST 3
#define A_BYTES (BM * 128)         // 16384
#define STAGE_BYTES (2 * A_BYTES)  // 32768
#define META_OFF (NST * STAGE_BYTES)      // 98304
#define SMEM_TOTAL (META_OFF + 1536)

__global__ __launch_bounds__(256, 2) void moe_gemm(
    const float* __restrict__ eb,   // [E, H]
    float*       __restrict__ out)  // [B, H]
{
    const int e  = blockIdx.z;
    const int ne = d_cnt[e];
    const int m0 = blockIdx.y * BM;
    if (m0 >= ne) return;
    const int n0 = blockIdx.x * BN;

    extern __shared__ char smem[];
    int*   stok_s  = (int*)  (smem + META_OFF);
    float* swt_s   = (float*)(smem + META_OFF + 512);
    float* sbias_s = (float*)(smem + META_OFF + 1024);

    const int tid = threadIdx.x;
    const int wid = tid >> 5, lid = tid & 31;
    const int g = lid >> 2, t = lid & 3;
    const int wm = wid >> 2, wn = wid & 3;    // 2 x 4 warp grid, tile 64x32

    if (tid < BM) {
        int m = m0 + tid;
        bool v = (m < ne);
        stok_s[tid] = v ? d_tok[e * BTOK + m] : d_tok[e * BTOK];
        swt_s [tid] = v ? d_wt [e * BTOK + m] : 0.f;
        sbias_s[tid] = eb[(size_t)e * HDIM + n0 + tid];
    }
    __syncthreads();

    const uint32_t sb = smem_u32(smem);
    const __half* Bbase = d_Wh + ((size_t)e * HDIM + n0) * DDIM;

    const int ldrow = tid >> 3;          // 0..31 (+32*i)
    const int ldcc  = tid & 7;           // 16B chunk in row

    auto load_stage = [&](int c) {
        const uint32_t stg = sb + (uint32_t)(c % NST) * STAGE_BYTES;
        const int k0 = c * BK;
#pragma unroll
        for (int i = 0; i < 4; i++) {
            int row = ldrow + 32 * i;
            const __half* src = d_Xh + (size_t)stok_s[row] * DDIM + k0 + ldcc * 8;
            CPASYNC16(stg + (uint32_t)(row * 128 + ((ldcc ^ (row & 7)) * 16)), src);
        }
        const uint32_t stgB = stg + A_BYTES;
#pragma unroll
        for (int i = 0; i < 4; i++) {
            int row = ldrow + 32 * i;
            const __half* src = Bbase + (size_t)row * DDIM + k0 + ldcc * 8;
            CPASYNC16(stgB + (uint32_t)(row * 128 + ((ldcc ^ (row & 7)) * 16)), src);
        }
    };

    const int rowA_in = lid & 15;
    const int kA      = lid >> 4;
    const int rowB_in = (lid & 7) + ((lid >> 4) & 1) * 8;
    const int kB      = (lid >> 3) & 1;

    float acc[4][4][4];
#pragma unroll
    for (int mf = 0; mf < 4; mf++)
#pragma unroll
        for (int nf = 0; nf < 4; nf++)
#pragma unroll
            for (int k = 0; k < 4; k++) acc[mf][nf][k] = 0.f;

#pragma unroll
    for (int p = 0; p < NST - 1; p++) { load_stage(p); CPCOMMIT(); }

    for (int kt = 0; kt < NCH; kt++) {
        CPWAIT(NST - 2);
        __syncthreads();
        if (kt + NST - 1 < NCH) load_stage(kt + NST - 1);
        CPCOMMIT();

        const uint32_t As = sb + (uint32_t)(kt % NST) * STAGE_BYTES;
        const uint32_t Bs = As + A_BYTES;

#pragma unroll
        for (int kss = 0; kss < 4; kss++) {
            // per-warp staggered sub-chunk: warps start at different ks phases,
            // so LDS bursts and MMA bursts interleave across warps.
            const int ks = (kss + wid) & 3;
            uint32_t a[4][4], b[4][2];
#pragma unroll
            for (int mf = 0; mf < 4; mf++) {
                const int row = wm * 64 + mf * 16 + rowA_in;
                const int cc  = 2 * ks + kA;
                ldsm_x4(a[mf][0], a[mf][1], a[mf][2], a[mf][3],
                        As + (uint32_t)(row * 128 + ((cc ^ (row & 7)) * 16)));
            }
#pragma unroll
            for (int nf2 = 0; nf2 < 2; nf2++) {
                const int row = wn * 32 + nf2 * 16 + rowB_in;
                const int cc  = 2 * ks + kB;
                ldsm_x4(b[2 * nf2][0], b[2 * nf2][1],
                        b[2 * nf2 + 1][0], b[2 * nf2 + 1][1],
                        Bs + (uint32_t)(row * 128 + ((cc ^ (row & 7)) * 16)));
            }
#pragma unroll
            for (int mf = 0; mf < 4; mf++)
#pragma unroll
                for (int nf = 0; nf < 4; nf++)
                    mma_f16(acc[mf][nf], a[mf], b[nf]);
        }
    }

    // epilogue: wt * (acc + bias) scattered via vector RED
#pragma unroll
    for (int mf = 0; mf < 4; mf++) {
        const int lr0 = wm * 64 + mf * 16 + g;
        const int lr1 = lr0 + 8;
        const bool v0 = (m0 + lr0) < ne;
        const bool v1 = (m0 + lr1) < ne;
        const float w0 = swt_s[lr0], w1 = swt_s[lr1];
        float* op0 = out + (size_t)stok_s[lr0] * HDIM + n0;
        float* op1 = out + (size_t)stok_s[lr1] * HDIM + n0;
#pragma unroll
        for (int nf = 0; nf < 4; nf++) {
            const int col = wn * 32 + nf * 8 + t * 2;
            const float b0 = sbias_s[col], b1 = sbias_s[col + 1];
            if (v0) {
                float2 v = make_float2(w0 * (acc[mf][nf][0] + b0),
                                       w0 * (acc[mf][nf][1] + b1));
                atomicAdd((float2*)(op0 + col), v);
            }
            if (v1) {
                float2 v = make_float2(w1 * (acc[mf][nf][2] + b0),
                                       w1 * (acc[mf][nf][3] + b1));
                atomicAdd((float2*)(op1 + col), v);
            }
        }
    }
}

// ---------------------------------------------------------------------------
// Launch
// ---------------------------------------------------------------------------
extern "C" void kernel_launch(void* const* d_in, const int* in_sizes, int n_in,
                              void* d_out, int out_size)
{
    const float* x      = (const float*)d_in[0];
    const int*   labels = (const int*)  d_in[1];
    const float* emb    = (const float*)d_in[2];
    const float* gw     = (const float*)d_in[3];
    const float* gb     = (const float*)d_in[4];
    const float* eW     = (const float*)d_in[5];
    const float* ebias  = (const float*)d_in[6];
    float* out = (float*)d_out;

    const size_t main_elems = (size_t)BTOK * HDIM;
    float* tail = ((size_t)out_size >= main_elems + 2 * BTOK)
                      ? out + main_elems : nullptr;

    static int inited = 0;
    static void* cnt_addr = nullptr;
    if (!inited) {
        cudaFuncSetAttribute(moe_gemm, cudaFuncAttributeMaxDynamicSharedMemorySize,
                             SMEM_TOTAL);
        cudaGetSymbolAddress(&cnt_addr, d_cnt);
        inited = 1;
    }

    cudaMemsetAsync(cnt_addr, 0, NEXP * sizeof(int), 0);
    prep_kernel<<<PREP_B, 256>>>(x, labels, emb, gw, gb, eW, out, tail);
    moe_gemm   <<<dim3(HDIM / BN, BTOK / BM, NEXP), 256, SMEM_TOTAL>>>(ebias, out);
}

// round 17
// speedup vs baseline: 1.0302x; 1.0302x over previous
#include <cuda_runtime.h>
#include <cuda_fp16.h>
#include <math.h>
#include <stdint.h>

#define BTOK 4096
#define DDIM 2048
#define HDIM 4096
#define NEXP 8

// ---------------------------------------------------------------------------
// Device-global scratch (no allocation allowed)
// ---------------------------------------------------------------------------
__device__ int    d_cnt[NEXP];
__device__ int    d_tok[NEXP * BTOK];
__device__ float  d_wt [NEXP * BTOK];
__device__ __half d_Xh [(size_t)BTOK * DDIM];          // fp16 activations (16MB)
__device__ __half d_Wh [(size_t)NEXP * HDIM * DDIM];   // fp16 weights (128MB)

// ---------------------------------------------------------------------------
// helpers
// ---------------------------------------------------------------------------
__device__ __forceinline__ uint32_t smem_u32(const void* p) {
    uint32_t a;
    asm("{ .reg .u64 t; cvta.to.shared.u64 t, %1; cvt.u32.u64 %0, t; }" : "=r"(a) : "l"(p));
    return a;
}
#define CPASYNC16(dst, src) \
    asm volatile("cp.async.cg.shared.global [%0], [%1], 16;" :: "r"(dst), "l"(src))
#define CPCOMMIT() asm volatile("cp.async.commit_group;" ::: "memory")
#define CPWAIT(n)  asm volatile("cp.async.wait_group %0;" :: "n"(n) : "memory")

__device__ __forceinline__ void ldsm_x4(uint32_t& r0, uint32_t& r1,
                                        uint32_t& r2, uint32_t& r3, uint32_t addr) {
    asm volatile("ldmatrix.sync.aligned.m8n8.x4.shared.b16 {%0,%1,%2,%3}, [%4];"
                 : "=r"(r0), "=r"(r1), "=r"(r2), "=r"(r3) : "r"(addr));
}

__device__ __forceinline__ void mma_f16(float* c, const uint32_t* a, const uint32_t* b) {
    asm volatile(
        "mma.sync.aligned.m16n8k16.row.col.f32.f16.f16.f32 "
        "{%0,%1,%2,%3}, {%4,%5,%6,%7}, {%8,%9}, {%0,%1,%2,%3};"
        : "+f"(c[0]), "+f"(c[1]), "+f"(c[2]), "+f"(c[3])
        : "r"(a[0]), "r"(a[1]), "r"(a[2]), "r"(a[3]), "r"(b[0]), "r"(b[1]));
}

__device__ __forceinline__ uint2 cvt_f4(float4 v) {
    __half2 h0 = __floats2half2_rn(v.x, v.y);
    __half2 h1 = __floats2half2_rn(v.z, v.w);
    return make_uint2(*(uint32_t*)&h0, *(uint32_t*)&h1);
}

// ---------------------------------------------------------------------------
// Kernel 1: fused prep — role split by blockIdx.x (frozen: at DRAM roofline)
// ---------------------------------------------------------------------------
#define GATE_B 4096
#define ZERO_B 1024
#define WC_B   4096
#define PREP_B (GATE_B + ZERO_B + WC_B)

__global__ __launch_bounds__(256) void prep_kernel(
    const float* __restrict__ x, const int* __restrict__ labels,
    const float* __restrict__ emb, const float* __restrict__ gw,
    const float* __restrict__ gb, const float* __restrict__ eW,
    float* __restrict__ out, float* __restrict__ out_tail)
{
    const int bid = blockIdx.x;
    const int tid = threadIdx.x;

    if (bid >= GATE_B) {
        int r = bid - GATE_B;
        if (r < ZERO_B) {
            float4* o4 = (float4*)out;
            const size_t stride = (size_t)ZERO_B * 256;
            size_t base = (size_t)r * 256 + tid;
            const float4 z = make_float4(0.f, 0.f, 0.f, 0.f);
#pragma unroll
            for (int it = 0; it < 4; it++) {
                o4[base]              = z;
                o4[base + stride]     = z;
                o4[base + 2 * stride] = z;
                o4[base + 3 * stride] = z;
                base += 4 * stride;
            }
            return;
        }
        r -= ZERO_B;
        {
            const float4* W4 = (const float4*)eW;
            uint2* D4 = (uint2*)d_Wh;
            const size_t stride = (size_t)WC_B * 256;
            size_t base = (size_t)r * 256 + tid;
#pragma unroll
            for (int it = 0; it < 4; it++) {
                float4 v0 = W4[base];
                float4 v1 = W4[base + stride];
                float4 v2 = W4[base + 2 * stride];
                float4 v3 = W4[base + 3 * stride];
                D4[base]              = cvt_f4(v0);
                D4[base + stride]     = cvt_f4(v1);
                D4[base + 2 * stride] = cvt_f4(v2);
                D4[base + 3 * stride] = cvt_f4(v3);
                base += 4 * stride;
            }
            return;
        }
    }

    // ---- gate role (+ fp16 x emission) ----
    const int b = bid;
    const float4* xr = (const float4*)(x   + (size_t)b * DDIM);
    const float4* er = (const float4*)(emb + (size_t)labels[b] * DDIM);
    uint2* xh = (uint2*)(d_Xh + (size_t)b * DDIM);

    float acc[NEXP];
#pragma unroll
    for (int e = 0; e < NEXP; e++) acc[e] = 0.f;

    for (int j = tid; j < DDIM / 4; j += 256) {
        float4 xv = xr[j];
        float4 ev = er[j];
        xh[j] = cvt_f4(xv);
#pragma unroll
        for (int e = 0; e < NEXP; e++) {
            const float4* g  = (const float4*)(gw + (size_t)e * 2 * DDIM);
            float4 g1 = g[j];
            float4 g2 = g[DDIM / 4 + j];
            acc[e] += xv.x * g1.x + xv.y * g1.y + xv.z * g1.z + xv.w * g1.w
                    + ev.x * g2.x + ev.y * g2.y + ev.z * g2.z + ev.w * g2.w;
        }
    }
#pragma unroll
    for (int e = 0; e < NEXP; e++)
#pragma unroll
        for (int o = 16; o > 0; o >>= 1)
            acc[e] += __shfl_xor_sync(0xffffffffu, acc[e], o);

    __shared__ float red[8][NEXP];
    const int w = tid >> 5, l = tid & 31;
    if (l == 0) {
#pragma unroll
        for (int e = 0; e < NEXP; e++) red[w][e] = acc[e];
    }
    __syncthreads();

    if (tid == 0) {
        float lg[NEXP];
#pragma unroll
        for (int e = 0; e < NEXP; e++) {
            float s = gb[e];
#pragma unroll
            for (int ww = 0; ww < 8; ww++) s += red[ww][e];
            lg[e] = s;
        }
        int i0 = 0;
#pragma unroll
        for (int e = 1; e < NEXP; e++) if (lg[e] > lg[i0]) i0 = e;
        int i1 = -1;
#pragma unroll
        for (int e = 0; e < NEXP; e++) {
            if (e == i0) continue;
            if (i1 < 0 || lg[e] > lg[i1]) i1 = e;
        }
        float p0 = 1.f / (1.f + expf(lg[i1] - lg[i0]));
        float p1 = 1.f - p0;

        int s0 = atomicAdd(&d_cnt[i0], 1);
        d_tok[i0 * BTOK + s0] = b;
        d_wt [i0 * BTOK + s0] = p0;
        int s1 = atomicAdd(&d_cnt[i1], 1);
        d_tok[i1 * BTOK + s1] = b;
        d_wt [i1 * BTOK + s1] = p1;

        if (out_tail) {
            out_tail[2 * b + 0] = (float)i0;
            out_tail[2 * b + 1] = (float)i1;
        }
    }
}

// ---------------------------------------------------------------------------
// Kernel 2: grouped fp16 mma.sync GEMM + weighted combine.
// Tile 128x128x64, 4 warps (2x2 grid of 64x64 warp tiles), 3-stage cp.async,
// 2 CTAs/SM. Halves LDSM bytes per MMA vs the 64x32 tiling while keeping
// 2-CTA co-residency for stall de-correlation.
// grid: (HDIM/128, BTOK/128, NEXP), 128 threads.
// ---------------------------------------------------------------------------
#define BM 128
#define BN 128
#define BK 64                      // halves; row = 128B
#define NCH (DDIM / BK)            // 32
#define NST 3
#define A_BYTES (BM * 128)         // 16384
#define STAGE_BYTES (2 * A_BYTES)  // 32768
#define META_OFF (NST * STAGE_BYTES)      // 98304
#define SMEM_TOTAL (META_OFF + 1536)

__global__ __launch_bounds__(128, 2) void moe_gemm(
    const float* __restrict__ eb,   // [E, H]
    float*       __restrict__ out)  // [B, H]
{
    const int e  = blockIdx.z;
    const int ne = d_cnt[e];
    const int m0 = blockIdx.y * BM;
    if (m0 >= ne) return;
    const int n0 = blockIdx.x * BN;

    extern __shared__ char smem[];
    int*   stok_s  = (int*)  (smem + META_OFF);
    float* swt_s   = (float*)(smem + META_OFF + 512);
    float* sbias_s = (float*)(smem + META_OFF + 1024);

    const int tid = threadIdx.x;
    const int wid = tid >> 5, lid = tid & 31;
    const int g = lid >> 2, t = lid & 3;
    const int wm = wid >> 1, wn = wid & 1;    // 2 x 2 warp grid, tile 64x64

    // meta: 128 threads load 128 rows / 128 bias entries
    {
        int m = m0 + tid;
        bool v = (m < ne);
        stok_s[tid] = v ? d_tok[e * BTOK + m] : d_tok[e * BTOK];
        swt_s [tid] = v ? d_wt [e * BTOK + m] : 0.f;
        sbias_s[tid] = eb[(size_t)e * HDIM + n0 + tid];
    }
    __syncthreads();

    const uint32_t sb = smem_u32(smem);
    const __half* Bbase = d_Wh + ((size_t)e * HDIM + n0) * DDIM;

    const int ldrow = tid >> 3;          // 0..15 (+16*i)
    const int ldcc  = tid & 7;           // 16B chunk in row

    auto load_stage = [&](int c) {
        const uint32_t stg = sb + (uint32_t)(c % NST) * STAGE_BYTES;
        const int k0 = c * BK;
#pragma unroll
        for (int i = 0; i < 8; i++) {
            int row = ldrow + 16 * i;    // 0..127
            const __half* src = d_Xh + (size_t)stok_s[row] * DDIM + k0 + ldcc * 8;
            CPASYNC16(stg + (uint32_t)(row * 128 + ((ldcc ^ (row & 7)) * 16)), src);
        }
        const uint32_t stgB = stg + A_BYTES;
#pragma unroll
        for (int i = 0; i < 8; i++) {
            int row = ldrow + 16 * i;    // 0..127
            const __half* src = Bbase + (size_t)row * DDIM + k0 + ldcc * 8;
            CPASYNC16(stgB + (uint32_t)(row * 128 + ((ldcc ^ (row & 7)) * 16)), src);
        }
    };

    const int rowA_in = lid & 15;
    const int kA      = lid >> 4;
    const int rowB_in = (lid & 7) + ((lid >> 4) & 1) * 8;
    const int kB      = (lid >> 3) & 1;

    float acc[4][8][4];
#pragma unroll
    for (int mf = 0; mf < 4; mf++)
#pragma unroll
        for (int nf = 0; nf < 8; nf++)
#pragma unroll
            for (int k = 0; k < 4; k++) acc[mf][nf][k] = 0.f;

#pragma unroll
    for (int p = 0; p < NST - 1; p++) { load_stage(p); CPCOMMIT(); }

    for (int kt = 0; kt < NCH; kt++) {
        CPWAIT(NST - 2);
        __syncthreads();
        if (kt + NST - 1 < NCH) load_stage(kt + NST - 1);
        CPCOMMIT();

        const uint32_t As = sb + (uint32_t)(kt % NST) * STAGE_BYTES;
        const uint32_t Bs = As + A_BYTES;

#pragma unroll
        for (int ks = 0; ks < 4; ks++) {
            uint32_t a[4][4], b[8][2];
#pragma unroll
            for (int mf = 0; mf < 4; mf++) {
                const int row = wm * 64 + mf * 16 + rowA_in;
                const int cc  = 2 * ks + kA;
                ldsm_x4(a[mf][0], a[mf][1], a[mf][2], a[mf][3],
                        As + (uint32_t)(row * 128 + ((cc ^ (row & 7)) * 16)));
            }
#pragma unroll
            for (int nf2 = 0; nf2 < 4; nf2++) {
                const int row = wn * 64 + nf2 * 16 + rowB_in;
                const int cc  = 2 * ks + kB;
                ldsm_x4(b[2 * nf2][0], b[2 * nf2][1],
                        b[2 * nf2 + 1][0], b[2 * nf2 + 1][1],
                        Bs + (uint32_t)(row * 128 + ((cc ^ (row & 7)) * 16)));
            }
#pragma unroll
            for (int mf = 0; mf < 4; mf++)
#pragma unroll
                for (int nf = 0; nf < 8; nf++)
                    mma_f16(acc[mf][nf], a[mf], b[nf]);
        }
    }

    // epilogue: wt * (acc + bias) scattered via vector RED
#pragma unroll
    for (int mf = 0; mf < 4; mf++) {
        const int lr0 = wm * 64 + mf * 16 + g;
        const int lr1 = lr0 + 8;
        const bool v0 = (m0 + lr0) < ne;
        const bool v1 = (m0 + lr1) < ne;
        const float w0 = swt_s[lr0], w1 = swt_s[lr1];
        float* op0 = out + (size_t)stok_s[lr0] * HDIM + n0;
        float* op1 = out + (size_t)stok_s[lr1] * HDIM + n0;
#pragma unroll
        for (int nf = 0; nf < 8; nf++) {
            const int col = wn * 64 + nf * 8 + t * 2;
            const float b0 = sbias_s[col], b1 = sbias_s[col + 1];
            if (v0) {
                float2 v = make_float2(w0 * (acc[mf][nf][0] + b0),
                                       w0 * (acc[mf][nf][1] + b1));
                atomicAdd((float2*)(op0 + col), v);
            }
            if (v1) {
                float2 v = make_float2(w1 * (acc[mf][nf][2] + b0),
                                       w1 * (acc[mf][nf][3] + b1));
                atomicAdd((float2*)(op1 + col), v);
            }
        }
    }
}

// ---------------------------------------------------------------------------
// Launch
// ---------------------------------------------------------------------------
extern "C" void kernel_launch(void* const* d_in, const int* in_sizes, int n_in,
                              void* d_out, int out_size)
{
    const float* x      = (const float*)d_in[0];
    const int*   labels = (const int*)  d_in[1];
    const float* emb    = (const float*)d_in[2];
    const float* gw     = (const float*)d_in[3];
    const float* gb     = (const float*)d_in[4];
    const float* eW     = (const float*)d_in[5];
    const float* ebias  = (const float*)d_in[6];
    float* out = (float*)d_out;

    const size_t main_elems = (size_t)BTOK * HDIM;
    float* tail = ((size_t)out_size >= main_elems + 2 * BTOK)
                      ? out + main_elems : nullptr;

    static int inited = 0;
    static void* cnt_addr = nullptr;
    if (!inited) {
        cudaFuncSetAttribute(moe_gemm, cudaFuncAttributeMaxDynamicSharedMemorySize,
                             SMEM_TOTAL);
        cudaGetSymbolAddress(&cnt_addr, d_cnt);
        inited = 1;
    }

    cudaMemsetAsync(cnt_addr, 0, NEXP * sizeof(int), 0);
    prep_kernel<<<PREP_B, 256>>>(x, labels, emb, gw, gb, eW, out, tail);
    moe_gemm   <<<dim3(HDIM / BN, BTOK / BM, NEXP), 128, SMEM_TOTAL>>>(ebias, out);
}